// round 12
// baseline (speedup 1.0000x reference)
#include <cuda_runtime.h>

#define NPTS   16384
#define NB     1024
#define YB     64
#define XMIN   (-5.0f)
#define INVW   ((float)NB / 10.0f)
#define SLAB   512
#define NSLAB  (NPTS / SLAB)              // 32
#define CELL   128
#define NCELL  (NPTS / CELL)              // 128
#define PREPT  1024

typedef unsigned int u32;

// set 0 = predict, set 1 = target; pass p: queries = set p, refs = set 1-p
__device__ float4 g_pts[2][NPTS];         // x-slab then y-sorted (x,y,z, 0.5|p|^2)
__device__ float  g_mine[2][NPTS];        // min e after diag; final d2 after off
__device__ float4 g_ext[2][NCELL];        // per-cell (xmin, xmax, ymin, ymax)
__device__ float2 g_slx[2][NSLAB];        // per-slab (xmin, xmax)

__device__ __forceinline__ int bin_of(float x) {
    int b = (int)((x - XMIN) * INVW);
    return min(max(b, 0), NB - 1);
}

// ---------- K1: fused x-bin sort (validated R6-R11) ----------
__global__ void __launch_bounds__(PREPT)
k_prep(const float* __restrict__ pr, const float* __restrict__ tg) {
    __shared__ int sh[NB];
    const int s = blockIdx.x;
    const int tid = threadIdx.x;
    const float* __restrict__ src = s ? tg : pr;

    sh[tid] = 0;
    __syncthreads();
#pragma unroll
    for (int k = 0; k < NPTS / PREPT; k++) {
        int i = tid + k * PREPT;
        atomicAdd(&sh[bin_of(src[3 * i])], 1);
    }
    __syncthreads();
    for (int d = 1; d < NB; d <<= 1) {
        int v = sh[tid];
        if (tid >= d) v += sh[tid - d];
        __syncthreads();
        sh[tid] = v;
        __syncthreads();
    }
    {
        int excl = (tid > 0) ? sh[tid - 1] : 0;
        __syncthreads();
        sh[tid] = excl;
    }
    __syncthreads();
#pragma unroll
    for (int k = 0; k < NPTS / PREPT; k++) {
        int i = tid + k * PREPT;
        float x = src[3 * i], y = src[3 * i + 1], z = src[3 * i + 2];
        int pos = atomicAdd(&sh[bin_of(x)], 1);
        g_pts[s][pos] = make_float4(x, y, z, 0.5f * (x * x + y * y + z * z));
    }
}

// ---------- K2: y-sort each slab + per-cell boxes + slab x-extents ----------
__global__ void __launch_bounds__(SLAB)
k_ysort() {
    __shared__ float4 buf[SLAB];
    __shared__ int hist[YB];
    __shared__ int cur[YB];
    __shared__ float wred[16][4];          // per-warp xmin,xmax,ymin,ymax
    __shared__ float4 sext[4];             // per-cell ext within slab
    const int slab = blockIdx.x, set = blockIdx.y, tid = threadIdx.x;
    const int base = slab * SLAB;
    const int lane = tid & 31, wid = tid >> 5;

    float4 pt = g_pts[set][base + tid];
    if (tid < YB) hist[tid] = 0;
    __syncthreads();
    int yb = min(max((int)((pt.y - XMIN) * ((float)YB / 10.0f)), 0), YB - 1);
    atomicAdd(&hist[yb], 1);
    __syncthreads();
    if (tid == 0) {
        int acc = 0;
        for (int b = 0; b < YB; b++) { int v = hist[b]; cur[b] = acc; acc += v; }
    }
    __syncthreads();
    int pos = atomicAdd(&cur[yb], 1);
    buf[pos] = pt;
    __syncthreads();
    float4 sp = buf[tid];
    g_pts[set][base + tid] = sp;

    // per-warp reduction of x/y extents (warp w covers 32 consecutive sorted pts)
    float xn = sp.x, xm = sp.x, yn = sp.y, ym = sp.y;
#pragma unroll
    for (int o = 16; o > 0; o >>= 1) {
        xn = fminf(xn, __shfl_down_sync(0xFFFFFFFFu, xn, o));
        xm = fmaxf(xm, __shfl_down_sync(0xFFFFFFFFu, xm, o));
        yn = fminf(yn, __shfl_down_sync(0xFFFFFFFFu, yn, o));
        ym = fmaxf(ym, __shfl_down_sync(0xFFFFFFFFu, ym, o));
    }
    if (lane == 0) { wred[wid][0] = xn; wred[wid][1] = xm; wred[wid][2] = yn; wred[wid][3] = ym; }
    __syncthreads();
    if (tid < 4) {                          // cell tid = warps 4*tid..4*tid+3
        float cxn = wred[4 * tid][0], cxm = wred[4 * tid][1];
        float cyn = wred[4 * tid][2], cym = wred[4 * tid][3];
#pragma unroll
        for (int w = 1; w < 4; w++) {
            cxn = fminf(cxn, wred[4 * tid + w][0]);
            cxm = fmaxf(cxm, wred[4 * tid + w][1]);
            cyn = fminf(cyn, wred[4 * tid + w][2]);
            cym = fmaxf(cym, wred[4 * tid + w][3]);
        }
        float4 e = make_float4(cxn, cxm, cyn, cym);
        sext[tid] = e;
        g_ext[set][slab * 4 + tid] = e;
    }
    __syncthreads();
    if (tid == 0) {
        float sxn = fminf(fminf(sext[0].x, sext[1].x), fminf(sext[2].x, sext[3].x));
        float sxm = fmaxf(fmaxf(sext[0].y, sext[1].y), fmaxf(sext[2].y, sext[3].y));
        g_slx[set][slab] = make_float2(sxn, sxm);
    }
}

// ---------- K3: diagonal band — one block per (cell, pass), 3 slabs ----------
__global__ void __launch_bounds__(CELL)
k_diag() {
    const int qc = blockIdx.x, pass = blockIdx.y, tid = threadIdx.x;
    __shared__ float4 sref[SLAB];

    const int qp = qc * CELL + tid;
    const float4 q = g_pts[pass][qp];
    const float nx = -q.x, ny = -q.y, nz = -q.z;
    const int qslab = qc >> 2;
    const float4* __restrict__ refs = g_pts[1 - pass];

    const float INF = __int_as_float(0x7f800000);
    float m0 = INF, m1 = INF;

#pragma unroll
    for (int sd = -1; sd <= 1; sd++) {
        int rs = qslab + sd;
        if (rs < 0 || rs >= NSLAB) continue;   // block-uniform
        __syncthreads();
#pragma unroll
        for (int k = 0; k < SLAB / CELL; k++)
            sref[tid + k * CELL] = refs[rs * SLAB + tid + k * CELL];
        __syncthreads();
#pragma unroll 4
        for (int j = 0; j < SLAB; j += 2) {
            float4 t0 = sref[j];
            float4 t1 = sref[j + 1];
            float e;
            e = __fmaf_rn(nx, t0.x, t0.w); e = __fmaf_rn(ny, t0.y, e); e = __fmaf_rn(nz, t0.z, e);
            m0 = fminf(m0, e);
            e = __fmaf_rn(nx, t1.x, t1.w); e = __fmaf_rn(ny, t1.y, e); e = __fmaf_rn(nz, t1.z, e);
            m1 = fminf(m1, e);
        }
    }
    g_mine[pass][qp] = fminf(m0, m1);          // plain store (block owns cell)
}

// ---------- K4: outward sweep with per-lane pruning ----------
__global__ void __launch_bounds__(CELL)
k_off() {
    const int qc = blockIdx.x, p = blockIdx.y, tid = threadIdx.x;
    const int rset = 1 - p;
    __shared__ float4 sref[CELL];

    const int qp = qc * CELL + tid;
    const float4 q = g_pts[p][qp];
    const float nx = -q.x, ny = -q.y, nz = -q.z;
    const int qslab = qc >> 2;
    const float4* __restrict__ refs = g_pts[rset];

    float m = g_mine[p][qp];
    float d2 = 2.0f * (m + q.w);               // running personal bound (unclamped)

#pragma unroll
    for (int dir = 0; dir < 2; dir++) {
        const int step = dir ? -1 : 1;
        for (int s = qslab + 2 * step; s >= 0 && s < NSLAB; s += step) {
            float2 sx = g_slx[rset][s];
            float gap = (step > 0) ? (sx.x - q.x) : (q.x - sx.y);
            gap = fmaxf(gap, 0.0f);
            if (__syncthreads_count(gap * gap < d2) == 0) break;   // monotone in |s-qslab|

            for (int yc = 0; yc < 4; yc++) {
                int rc = 4 * s + yc;
                float4 bx = g_ext[rset][rc];
                float gx = fmaxf(fmaxf(bx.x - q.x, q.x - bx.y), 0.0f);
                float gy = fmaxf(fmaxf(bx.z - q.y, q.y - bx.w), 0.0f);
                int need = (gx * gx + gy * gy) < d2;
                if (__syncthreads_count(need) == 0) continue;      // also fences sref

                sref[tid] = refs[rc * CELL + tid];
                __syncthreads();

                if (__any_sync(0xFFFFFFFFu, need)) {
                    float m0 = m, m1 = __int_as_float(0x7f800000);
#pragma unroll 4
                    for (int j = 0; j < CELL; j += 2) {
                        float4 t0 = sref[j];
                        float4 t1 = sref[j + 1];
                        float e;
                        e = __fmaf_rn(nx, t0.x, t0.w); e = __fmaf_rn(ny, t0.y, e); e = __fmaf_rn(nz, t0.z, e);
                        m0 = fminf(m0, e);
                        e = __fmaf_rn(nx, t1.x, t1.w); e = __fmaf_rn(ny, t1.y, e); e = __fmaf_rn(nz, t1.z, e);
                        m1 = fminf(m1, e);
                    }
                    m = fminf(m0, m1);
                    d2 = 2.0f * (m + q.w);
                }
            }
        }
    }

    g_mine[p][qp] = fmaxf(2.0f * (m + q.w), 0.0f);   // final clamped d2
}

// ---------- K5: deterministic reduction ----------
__global__ void __launch_bounds__(1024)
k_reduce(float* __restrict__ out) {
    __shared__ float sh[1024];
    const float* d2 = (const float*)g_mine;   // 2*NPTS final distances
    float s = 0.0f;
    for (int i = threadIdx.x; i < 2 * NPTS; i += 1024)
        s += d2[i];
    sh[threadIdx.x] = s;
    __syncthreads();
#pragma unroll
    for (int o = 512; o > 0; o >>= 1) {
        if (threadIdx.x < o) sh[threadIdx.x] += sh[threadIdx.x + o];
        __syncthreads();
    }
    if (threadIdx.x == 0)
        out[0] = sh[0] * (1.0f / (float)NPTS);
}

extern "C" void kernel_launch(void* const* d_in, const int* in_sizes, int n_in,
                              void* d_out, int out_size) {
    const float* pr = (const float*)d_in[0];   // predict [1,16384,3]
    const float* tg = (const float*)d_in[1];   // target  [1,16384,3]
    float* out = (float*)d_out;

    k_prep<<<2, PREPT>>>(pr, tg);

    dim3 ygrid(NSLAB, 2);
    k_ysort<<<ygrid, SLAB>>>();

    dim3 dgrid(NCELL, 2);
    k_diag<<<dgrid, CELL>>>();

    dim3 ogrid(NCELL, 2);
    k_off<<<ogrid, CELL>>>();

    k_reduce<<<1, 1024>>>(out);
}

// round 13
// speedup vs baseline: 1.9881x; 1.9881x over previous
#include <cuda_runtime.h>

#define NPTS   16384
#define NB     1024
#define YB     64
#define XMIN   (-5.0f)
#define INVW   ((float)NB / 10.0f)
#define SLAB   512
#define NSLAB  (NPTS / SLAB)              // 32
#define CELL   128
#define NCELL  (NPTS / CELL)              // 128
#define NQW    (NPTS / 32)                // 512 query warps per set
#define PREPT  1024
#define OFFB   1024                       // k_off blocks (8 warps each)
#define MAXWORK (2 * NQW * NCELL)         // absolute worst case

typedef unsigned int u32;

// set 0 = predict, set 1 = target; pass p: queries = set p, refs = set 1-p
__device__ float4 g_pts[2][NPTS];         // x-slab then y-sorted (x,y,z, 0.5|p|^2)
__device__ u32    g_minbits[2][NPTS];     // flipped min-e
__device__ float4 g_ext[2][NCELL];        // per ref-cell box (xmin,xmax,ymin,ymax)
__device__ float4 g_wext[2][NQW];         // per query-warp box
__device__ int    g_nwork;
__device__ int    g_work[MAXWORK];        // p<<16 | qw<<7 | rc

__device__ __forceinline__ int bin_of(float x) {
    int b = (int)((x - XMIN) * INVW);
    return min(max(b, 0), NB - 1);
}
__device__ __forceinline__ u32 fflip(float f) {
    u32 u = __float_as_uint(f);
    return (u & 0x80000000u) ? ~u : (u | 0x80000000u);
}
__device__ __forceinline__ float funflip(u32 u) {
    u = (u & 0x80000000u) ? (u ^ 0x80000000u) : ~u;
    return __uint_as_float(u);
}

// ---------- K1: fused x-bin sort (validated R6-R12) ----------
__global__ void __launch_bounds__(PREPT)
k_prep(const float* __restrict__ pr, const float* __restrict__ tg) {
    __shared__ int sh[NB];
    const int s = blockIdx.x;
    const int tid = threadIdx.x;
    const float* __restrict__ src = s ? tg : pr;

    if (s == 0 && tid == 0) g_nwork = 0;

    sh[tid] = 0;
    __syncthreads();
#pragma unroll
    for (int k = 0; k < NPTS / PREPT; k++) {
        int i = tid + k * PREPT;
        atomicAdd(&sh[bin_of(src[3 * i])], 1);
    }
    __syncthreads();
    for (int d = 1; d < NB; d <<= 1) {
        int v = sh[tid];
        if (tid >= d) v += sh[tid - d];
        __syncthreads();
        sh[tid] = v;
        __syncthreads();
    }
    {
        int excl = (tid > 0) ? sh[tid - 1] : 0;
        __syncthreads();
        sh[tid] = excl;
    }
    __syncthreads();
#pragma unroll
    for (int k = 0; k < NPTS / PREPT; k++) {
        int i = tid + k * PREPT;
        float x = src[3 * i], y = src[3 * i + 1], z = src[3 * i + 2];
        int pos = atomicAdd(&sh[bin_of(x)], 1);
        g_pts[s][pos] = make_float4(x, y, z, 0.5f * (x * x + y * y + z * z));
        g_minbits[s][i] = 0xFFFFFFFFu;
    }
}

// ---------- K2: y-sort each slab + per-warp boxes + per-cell boxes ----------
__global__ void __launch_bounds__(SLAB)
k_ysort() {
    __shared__ float4 buf[SLAB];
    __shared__ int hist[YB];
    __shared__ int cur[YB];
    __shared__ float wred[16][4];
    const int slab = blockIdx.x, set = blockIdx.y, tid = threadIdx.x;
    const int base = slab * SLAB;
    const int lane = tid & 31, wid = tid >> 5;

    float4 pt = g_pts[set][base + tid];
    if (tid < YB) hist[tid] = 0;
    __syncthreads();
    int yb = min(max((int)((pt.y - XMIN) * ((float)YB / 10.0f)), 0), YB - 1);
    atomicAdd(&hist[yb], 1);
    __syncthreads();
    if (tid == 0) {
        int acc = 0;
        for (int b = 0; b < YB; b++) { int v = hist[b]; cur[b] = acc; acc += v; }
    }
    __syncthreads();
    int pos = atomicAdd(&cur[yb], 1);
    buf[pos] = pt;
    __syncthreads();
    float4 sp = buf[tid];
    g_pts[set][base + tid] = sp;

    // per-warp extents of the sorted points this warp covers
    float xn = sp.x, xm = sp.x, yn = sp.y, ym = sp.y;
#pragma unroll
    for (int o = 16; o > 0; o >>= 1) {
        xn = fminf(xn, __shfl_xor_sync(0xFFFFFFFFu, xn, o));
        xm = fmaxf(xm, __shfl_xor_sync(0xFFFFFFFFu, xm, o));
        yn = fminf(yn, __shfl_xor_sync(0xFFFFFFFFu, yn, o));
        ym = fmaxf(ym, __shfl_xor_sync(0xFFFFFFFFu, ym, o));
    }
    if (lane == 0) {
        g_wext[set][slab * 16 + wid] = make_float4(xn, xm, yn, ym);
        wred[wid][0] = xn; wred[wid][1] = xm; wred[wid][2] = yn; wred[wid][3] = ym;
    }
    __syncthreads();
    if (tid < 4) {                          // cell boxes (4 warps each)
        float cxn = wred[4 * tid][0], cxm = wred[4 * tid][1];
        float cyn = wred[4 * tid][2], cym = wred[4 * tid][3];
#pragma unroll
        for (int w = 1; w < 4; w++) {
            cxn = fminf(cxn, wred[4 * tid + w][0]);
            cxm = fmaxf(cxm, wred[4 * tid + w][1]);
            cyn = fminf(cyn, wred[4 * tid + w][2]);
            cym = fmaxf(cym, wred[4 * tid + w][3]);
        }
        g_ext[set][slab * 4 + tid] = make_float4(cxn, cxm, cyn, cym);
    }
}

// ---------- K3: diagonal band — wide grid (cell, slab-offset, pass) ----------
__global__ void __launch_bounds__(CELL)
k_diag() {
    const int qc = blockIdx.x;
    const int sd = (int)blockIdx.y - 1;
    const int pass = blockIdx.z;
    const int rslab = (qc >> 2) + sd;
    if (rslab < 0 || rslab >= NSLAB) return;
    const int tid = threadIdx.x;

    __shared__ float4 sref[SLAB];
    const float4* __restrict__ refs = g_pts[1 - pass];
    {
        int rb = rslab * SLAB;
#pragma unroll
        for (int k = 0; k < SLAB / CELL; k++)
            sref[tid + k * CELL] = refs[rb + tid + k * CELL];
    }

    const int qp = qc * CELL + tid;
    const float4 q = g_pts[pass][qp];
    const float nx = -q.x, ny = -q.y, nz = -q.z;
    __syncthreads();

    const float INF = __int_as_float(0x7f800000);
    float m0 = INF, m1 = INF;
#pragma unroll 4
    for (int j = 0; j < SLAB; j += 2) {
        float4 t0 = sref[j];
        float4 t1 = sref[j + 1];
        float e;
        e = __fmaf_rn(nx, t0.x, t0.w); e = __fmaf_rn(ny, t0.y, e); e = __fmaf_rn(nz, t0.z, e);
        m0 = fminf(m0, e);
        e = __fmaf_rn(nx, t1.x, t1.w); e = __fmaf_rn(ny, t1.y, e); e = __fmaf_rn(nz, t1.z, e);
        m1 = fminf(m1, e);
    }
    atomicMin(&g_minbits[pass][qp], fflip(fminf(m0, m1)));
}

// ---------- K4: fused per-warp bounds + worklist build ----------
// grid (NQW, 2), 32 threads: one query warp. Compute warp cmax from diag
// mins, then each lane tests 4 ref cells against the warp box.
__global__ void __launch_bounds__(32)
k_build() {
    const int qw = blockIdx.x, p = blockIdx.y, lane = threadIdx.x;
    const int qp = qw * 32 + lane;

    float4 q = g_pts[p][qp];
    float m = funflip(g_minbits[p][qp]);
    float d2 = fmaxf(2.0f * (m + q.w), 0.0f);
#pragma unroll
    for (int o = 16; o > 0; o >>= 1)
        d2 = fmaxf(d2, __shfl_xor_sync(0xFFFFFFFFu, d2, o));   // warp cmax

    const float4 wq = g_wext[p][qw];
    const int qslab = qw >> 4;

#pragma unroll
    for (int k = 0; k < 4; k++) {
        int rc = lane + 32 * k;
        int rs = rc >> 2;
        if (rs >= qslab - 1 && rs <= qslab + 1) continue;   // diag-covered
        float4 er = g_ext[1 - p][rc];
        float gx = fmaxf(fmaxf(er.x - wq.y, wq.x - er.y), 0.0f);
        float gy = fmaxf(fmaxf(er.z - wq.w, wq.z - er.w), 0.0f);
        if (gx * gx + gy * gy < d2) {
            int w = atomicAdd(&g_nwork, 1);
            g_work[w] = (p << 16) | (qw << 7) | rc;
        }
    }
}

// ---------- K5: flat warp-per-item off-diagonal eval ----------
__global__ void __launch_bounds__(256)
k_off() {
    __shared__ float4 sref[8][CELL];
    const int wid = threadIdx.x >> 5, lane = threadIdx.x & 31;
    const int gw = blockIdx.x * 8 + wid;
    const int n = g_nwork;
    const float INF = __int_as_float(0x7f800000);

    for (int w = gw; w < n; w += OFFB * 8) {
        const int e = g_work[w];                 // warp-uniform
        const int rc = e & 127;
        const int qw = (e >> 7) & 511;
        const int p = e >> 16;

        __syncwarp();                            // protect sref reuse
#pragma unroll
        for (int k = 0; k < 4; k++)
            sref[wid][lane + 32 * k] = g_pts[1 - p][rc * CELL + lane + 32 * k];
        __syncwarp();

        const int qp = qw * 32 + lane;
        const float4 q = g_pts[p][qp];
        const float nx = -q.x, ny = -q.y, nz = -q.z;

        float m0 = INF, m1 = INF;
#pragma unroll 4
        for (int j = 0; j < CELL; j += 2) {
            float4 t0 = sref[wid][j];
            float4 t1 = sref[wid][j + 1];
            float ev;
            ev = __fmaf_rn(nx, t0.x, t0.w); ev = __fmaf_rn(ny, t0.y, ev); ev = __fmaf_rn(nz, t0.z, ev);
            m0 = fminf(m0, ev);
            ev = __fmaf_rn(nx, t1.x, t1.w); ev = __fmaf_rn(ny, t1.y, ev); ev = __fmaf_rn(nz, t1.z, ev);
            m1 = fminf(m1, ev);
        }
        atomicMin(&g_minbits[p][qp], fflip(fminf(m0, m1)));
    }
}

// ---------- K6: deterministic reduction ----------
__global__ void __launch_bounds__(1024)
k_reduce(float* __restrict__ out) {
    __shared__ float sh[1024];
    float sum = 0.0f;
#pragma unroll
    for (int p = 0; p < 2; p++) {
        for (int i = threadIdx.x; i < NPTS; i += 1024) {
            float4 q = g_pts[p][i];
            float m = funflip(g_minbits[p][i]);
            sum += fmaxf(2.0f * (m + q.w), 0.0f);
        }
    }
    sh[threadIdx.x] = sum;
    __syncthreads();
#pragma unroll
    for (int o = 512; o > 0; o >>= 1) {
        if (threadIdx.x < o) sh[threadIdx.x] += sh[threadIdx.x + o];
        __syncthreads();
    }
    if (threadIdx.x == 0)
        out[0] = sh[0] * (1.0f / (float)NPTS);
}

extern "C" void kernel_launch(void* const* d_in, const int* in_sizes, int n_in,
                              void* d_out, int out_size) {
    const float* pr = (const float*)d_in[0];   // predict [1,16384,3]
    const float* tg = (const float*)d_in[1];   // target  [1,16384,3]
    float* out = (float*)d_out;

    k_prep<<<2, PREPT>>>(pr, tg);

    dim3 ygrid(NSLAB, 2);
    k_ysort<<<ygrid, SLAB>>>();

    dim3 dgrid(NCELL, 3, 2);
    k_diag<<<dgrid, CELL>>>();

    dim3 bgrid(NQW, 2);
    k_build<<<bgrid, 32>>>();

    k_off<<<OFFB, 256>>>();

    k_reduce<<<1, 1024>>>(out);
}

// round 14
// speedup vs baseline: 1.9917x; 1.0018x over previous
#include <cuda_runtime.h>

#define NPTS   16384
#define NB     1024
#define YB     64
#define XMIN   (-5.0f)
#define INVW   ((float)NB / 10.0f)
#define SLAB   512
#define NSLAB  (NPTS / SLAB)              // 32
#define CELL   128
#define NCELL  (NPTS / CELL)              // 128
#define NQW    (NPTS / 32)                // 512 query warps per set
#define PREPT  1024
#define OFFB   1024                       // k_off blocks (8 warps each)
#define MAXWORK (2 * NQW * NCELL)

typedef unsigned int u32;

// set 0 = predict, set 1 = target; pass p: queries = set p, refs = set 1-p
__device__ float4 g_pts[2][NPTS];         // x-slab then y-sorted (x,y,z, 0.5|p|^2)
__device__ u32    g_minbits[2][NPTS];     // flipped min-e
__device__ float4 g_ext[2][NCELL];        // per ref-cell box (xmin,xmax,ymin,ymax)
__device__ float4 g_wext[2][NQW];         // per query-warp box
__device__ int    g_nwork;
__device__ int    g_work[MAXWORK];        // p<<16 | qw<<7 | rc

__device__ __forceinline__ int bin_of(float x) {
    int b = (int)((x - XMIN) * INVW);
    return min(max(b, 0), NB - 1);
}
__device__ __forceinline__ u32 fflip(float f) {
    u32 u = __float_as_uint(f);
    return (u & 0x80000000u) ? ~u : (u | 0x80000000u);
}
__device__ __forceinline__ float funflip(u32 u) {
    u = (u & 0x80000000u) ? (u ^ 0x80000000u) : ~u;
    return __uint_as_float(u);
}

// ---------- K1: fused x-bin sort (validated R6-R13) ----------
__global__ void __launch_bounds__(PREPT)
k_prep(const float* __restrict__ pr, const float* __restrict__ tg) {
    __shared__ int sh[NB];
    const int s = blockIdx.x;
    const int tid = threadIdx.x;
    const float* __restrict__ src = s ? tg : pr;

    if (s == 0 && tid == 0) g_nwork = 0;

    sh[tid] = 0;
    __syncthreads();
#pragma unroll
    for (int k = 0; k < NPTS / PREPT; k++) {
        int i = tid + k * PREPT;
        atomicAdd(&sh[bin_of(src[3 * i])], 1);
    }
    __syncthreads();
    for (int d = 1; d < NB; d <<= 1) {
        int v = sh[tid];
        if (tid >= d) v += sh[tid - d];
        __syncthreads();
        sh[tid] = v;
        __syncthreads();
    }
    {
        int excl = (tid > 0) ? sh[tid - 1] : 0;
        __syncthreads();
        sh[tid] = excl;
    }
    __syncthreads();
#pragma unroll
    for (int k = 0; k < NPTS / PREPT; k++) {
        int i = tid + k * PREPT;
        float x = src[3 * i], y = src[3 * i + 1], z = src[3 * i + 2];
        int pos = atomicAdd(&sh[bin_of(x)], 1);
        g_pts[s][pos] = make_float4(x, y, z, 0.5f * (x * x + y * y + z * z));
    }
}

// ---------- K2: y-sort each slab + per-warp boxes + per-cell boxes ----------
__global__ void __launch_bounds__(SLAB)
k_ysort() {
    __shared__ float4 buf[SLAB];
    __shared__ int hist[YB];
    __shared__ int cur[YB];
    __shared__ float wred[16][4];
    const int slab = blockIdx.x, set = blockIdx.y, tid = threadIdx.x;
    const int base = slab * SLAB;
    const int lane = tid & 31, wid = tid >> 5;

    float4 pt = g_pts[set][base + tid];
    if (tid < YB) hist[tid] = 0;
    __syncthreads();
    int yb = min(max((int)((pt.y - XMIN) * ((float)YB / 10.0f)), 0), YB - 1);
    atomicAdd(&hist[yb], 1);
    __syncthreads();
    if (tid == 0) {
        int acc = 0;
        for (int b = 0; b < YB; b++) { int v = hist[b]; cur[b] = acc; acc += v; }
    }
    __syncthreads();
    int pos = atomicAdd(&cur[yb], 1);
    buf[pos] = pt;
    __syncthreads();
    float4 sp = buf[tid];
    g_pts[set][base + tid] = sp;

    float xn = sp.x, xm = sp.x, yn = sp.y, ym = sp.y;
#pragma unroll
    for (int o = 16; o > 0; o >>= 1) {
        xn = fminf(xn, __shfl_xor_sync(0xFFFFFFFFu, xn, o));
        xm = fmaxf(xm, __shfl_xor_sync(0xFFFFFFFFu, xm, o));
        yn = fminf(yn, __shfl_xor_sync(0xFFFFFFFFu, yn, o));
        ym = fmaxf(ym, __shfl_xor_sync(0xFFFFFFFFu, ym, o));
    }
    if (lane == 0) {
        g_wext[set][slab * 16 + wid] = make_float4(xn, xm, yn, ym);
        wred[wid][0] = xn; wred[wid][1] = xm; wred[wid][2] = yn; wred[wid][3] = ym;
    }
    __syncthreads();
    if (tid < 4) {
        float cxn = wred[4 * tid][0], cxm = wred[4 * tid][1];
        float cyn = wred[4 * tid][2], cym = wred[4 * tid][3];
#pragma unroll
        for (int w = 1; w < 4; w++) {
            cxn = fminf(cxn, wred[4 * tid + w][0]);
            cxm = fmaxf(cxm, wred[4 * tid + w][1]);
            cyn = fminf(cyn, wred[4 * tid + w][2]);
            cym = fmaxf(cym, wred[4 * tid + w][3]);
        }
        g_ext[set][slab * 4 + tid] = make_float4(cxn, cxm, cyn, cym);
    }
}

// ---------- K3: fused diag (3 slabs) + per-warp worklist build ----------
// One block per (cell, pass): block owns its 128 queries exclusively.
__global__ void __launch_bounds__(CELL)
k_diagbuild() {
    const int qc = blockIdx.x, p = blockIdx.y, tid = threadIdx.x;
    const int lane = tid & 31, w4 = tid >> 5;
    __shared__ float4 sref[SLAB];

    const int qp = qc * CELL + tid;
    const float4 q = g_pts[p][qp];
    const float nx = -q.x, ny = -q.y, nz = -q.z;
    const int qslab = qc >> 2;
    const float4* __restrict__ refs = g_pts[1 - p];

    const float INF = __int_as_float(0x7f800000);
    float m0 = INF, m1 = INF;

#pragma unroll
    for (int sd = -1; sd <= 1; sd++) {
        int rs = qslab + sd;
        if (rs < 0 || rs >= NSLAB) continue;   // block-uniform
        __syncthreads();
#pragma unroll
        for (int k = 0; k < SLAB / CELL; k++)
            sref[tid + k * CELL] = refs[rs * SLAB + tid + k * CELL];
        __syncthreads();
#pragma unroll 4
        for (int j = 0; j < SLAB; j += 2) {
            float4 t0 = sref[j];
            float4 t1 = sref[j + 1];
            float e;
            e = __fmaf_rn(nx, t0.x, t0.w); e = __fmaf_rn(ny, t0.y, e); e = __fmaf_rn(nz, t0.z, e);
            m0 = fminf(m0, e);
            e = __fmaf_rn(nx, t1.x, t1.w); e = __fmaf_rn(ny, t1.y, e); e = __fmaf_rn(nz, t1.z, e);
            m1 = fminf(m1, e);
        }
    }
    float m = fminf(m0, m1);
    g_minbits[p][qp] = fflip(m);               // exclusive owner: plain store

    // ---- inline build: per-warp cmax + box tests ----
    float d2 = fmaxf(2.0f * (m + q.w), 0.0f);
#pragma unroll
    for (int o = 16; o > 0; o >>= 1)
        d2 = fmaxf(d2, __shfl_xor_sync(0xFFFFFFFFu, d2, o));   // warp cmax

    const int qw = qc * 4 + w4;
    const float4 wq = g_wext[p][qw];

#pragma unroll
    for (int k = 0; k < 4; k++) {
        int rc = lane + 32 * k;
        int rs = rc >> 2;
        if (rs >= qslab - 1 && rs <= qslab + 1) continue;   // diag-covered
        float4 er = g_ext[1 - p][rc];
        float gx = fmaxf(fmaxf(er.x - wq.y, wq.x - er.y), 0.0f);
        float gy = fmaxf(fmaxf(er.z - wq.w, wq.z - er.w), 0.0f);
        if (gx * gx + gy * gy < d2) {
            int w = atomicAdd(&g_nwork, 1);
            g_work[w] = (p << 16) | (qw << 7) | rc;
        }
    }
}

// ---------- K4: flat warp-per-item off-diagonal eval (validated R13) ----------
__global__ void __launch_bounds__(256)
k_off() {
    __shared__ float4 sref[8][CELL];
    const int wid = threadIdx.x >> 5, lane = threadIdx.x & 31;
    const int gw = blockIdx.x * 8 + wid;
    const int n = g_nwork;
    const float INF = __int_as_float(0x7f800000);

    for (int w = gw; w < n; w += OFFB * 8) {
        const int e = g_work[w];                 // warp-uniform
        const int rc = e & 127;
        const int qw = (e >> 7) & 511;
        const int p = e >> 16;

        __syncwarp();
#pragma unroll
        for (int k = 0; k < 4; k++)
            sref[wid][lane + 32 * k] = g_pts[1 - p][rc * CELL + lane + 32 * k];
        __syncwarp();

        const int qp = qw * 32 + lane;
        const float4 q = g_pts[p][qp];
        const float nx = -q.x, ny = -q.y, nz = -q.z;

        float m0 = INF, m1 = INF;
#pragma unroll 4
        for (int j = 0; j < CELL; j += 2) {
            float4 t0 = sref[wid][j];
            float4 t1 = sref[wid][j + 1];
            float ev;
            ev = __fmaf_rn(nx, t0.x, t0.w); ev = __fmaf_rn(ny, t0.y, ev); ev = __fmaf_rn(nz, t0.z, ev);
            m0 = fminf(m0, ev);
            ev = __fmaf_rn(nx, t1.x, t1.w); ev = __fmaf_rn(ny, t1.y, ev); ev = __fmaf_rn(nz, t1.z, ev);
            m1 = fminf(m1, ev);
        }
        atomicMin(&g_minbits[p][qp], fflip(fminf(m0, m1)));
    }
}

// ---------- K5: deterministic reduction ----------
__global__ void __launch_bounds__(1024)
k_reduce(float* __restrict__ out) {
    __shared__ float sh[1024];
    float sum = 0.0f;
#pragma unroll
    for (int p = 0; p < 2; p++) {
        for (int i = threadIdx.x; i < NPTS; i += 1024) {
            float4 q = g_pts[p][i];
            float m = funflip(g_minbits[p][i]);
            sum += fmaxf(2.0f * (m + q.w), 0.0f);
        }
    }
    sh[threadIdx.x] = sum;
    __syncthreads();
#pragma unroll
    for (int o = 512; o > 0; o >>= 1) {
        if (threadIdx.x < o) sh[threadIdx.x] += sh[threadIdx.x + o];
        __syncthreads();
    }
    if (threadIdx.x == 0)
        out[0] = sh[0] * (1.0f / (float)NPTS);
}

extern "C" void kernel_launch(void* const* d_in, const int* in_sizes, int n_in,
                              void* d_out, int out_size) {
    const float* pr = (const float*)d_in[0];   // predict [1,16384,3]
    const float* tg = (const float*)d_in[1];   // target  [1,16384,3]
    float* out = (float*)d_out;

    k_prep<<<2, PREPT>>>(pr, tg);

    dim3 ygrid(NSLAB, 2);
    k_ysort<<<ygrid, SLAB>>>();

    dim3 dgrid(NCELL, 2);
    k_diagbuild<<<dgrid, CELL>>>();

    k_off<<<OFFB, 256>>>();

    k_reduce<<<1, 1024>>>(out);
}